// round 5
// baseline (speedup 1.0000x reference)
#include <cuda_runtime.h>

// Warp1DOp via smem row staging.
// Block = one (n,h) row, 320 threads, 4 pixels/thread. Per channel:
//   coalesced LDG.128 of the img row -> STS.128 into a padded smem buffer
//   (double-buffered), then random-access LDS gather + FMA + STG.128.
// All GLOBAL traffic is unit-stride; the scatter lives entirely in smem.
//
// Padded buffer layout: buf[4 + j] = img_row[j] for j in [0,1280);
// buf[3] = buf[1284] = 0 are the zeros-padding columns. Gather index
// idx = x0 + 3 where x0 = floor(clip(w - disp, -1, W) + 1) in [0, 1281],
// so idx in [3, 1284] -- always in range, no predication.

#define N_ 4
#define C_ 32
#define H_ 384
#define W_ 1280
#define HW_ (H_ * W_)
#define CHW_ (C_ * HW_)
#define NH_ (N_ * H_)
#define THREADS_ 320          // W_/4

__global__ __launch_bounds__(THREADS_) void warp1d_kernel(
    const float* __restrict__ img,
    const float* __restrict__ disp,
    float* __restrict__ out)
{
    __shared__ float buf[2][1288];

    const int t  = threadIdx.x;
    const int nh = blockIdx.x;            // n*H + h
    const int w  = t * 4;

    // zero the padding slots of both buffers (never overwritten after)
    if (t < 2) {
        buf[t][3]    = 0.0f;
        buf[t][1284] = 0.0f;
    }

    // ---- per-pixel coordinate math (once, reused for all 32 channels) ----
    const float* __restrict__ drow = disp + (size_t)nh * W_;
    float4 d4 = *reinterpret_cast<const float4*>(drow + w);
    float dv[4] = {d4.x, d4.y, d4.z, d4.w};

    int   i0[4], i1[4];
    float dx[4], mdx[4];
#pragma unroll
    for (int i = 0; i < 4; ++i) {
        float x = (float)(w + i) - dv[i];
        x = fminf(fmaxf(x, -1.0f), (float)W_) + 1.0f;   // [0, W+1]
        float xf = floorf(x);
        int   p0 = (int)xf;
        float f  = x - xf;
        int   p1 = p0 + (f > 0.0f ? 1 : 0);             // == ceil(x)
        i0[i]  = p0 + 3;                                 // smem gather index
        i1[i]  = p1 + 3;
        dx[i]  = f;
        mdx[i] = 1.0f - f;
    }

    const size_t base = (size_t)(nh / H_) * CHW_ + (size_t)(nh % H_) * W_;
    const float* __restrict__ irow = img + base;
    float* __restrict__ orow = out + base + w;

    // ---- preload channel 0 into buf[0] ----
    float4 v0 = *reinterpret_cast<const float4*>(irow + w);
    *reinterpret_cast<float4*>(&buf[0][4 + w]) = v0;
    __syncthreads();

#pragma unroll 2
    for (int c = 0; c < C_; ++c) {
        // issue next channel's coalesced load early (latency hidden by gather)
        float4 nx;
        if (c + 1 < C_)
            nx = *reinterpret_cast<const float4*>(irow + (size_t)(c + 1) * HW_ + w);

        const float* __restrict__ b = buf[c & 1];
        float a0 = b[i0[0]], q0 = b[i1[0]];
        float a1 = b[i0[1]], q1 = b[i1[1]];
        float a2 = b[i0[2]], q2 = b[i1[2]];
        float a3 = b[i0[3]], q3 = b[i1[3]];

        float4 o;
        o.x = mdx[0] * a0 + dx[0] * q0;
        o.y = mdx[1] * a1 + dx[1] * q1;
        o.z = mdx[2] * a2 + dx[2] * q2;
        o.w = mdx[3] * a3 + dx[3] * q3;
        *reinterpret_cast<float4*>(orow + (size_t)c * HW_) = o;

        if (c + 1 < C_)
            *reinterpret_cast<float4*>(&buf[(c + 1) & 1][4 + w]) = nx;
        __syncthreads();
    }
}

extern "C" void kernel_launch(void* const* d_in, const int* in_sizes, int n_in,
                              void* d_out, int out_size)
{
    const float* img  = (const float*)d_in[0];
    const float* disp = (const float*)d_in[1];
    float* out = (float*)d_out;

    warp1d_kernel<<<NH_, THREADS_>>>(img, disp, out);
}